// round 5
// baseline (speedup 1.0000x reference)
#include <cuda_runtime.h>
#include <math.h>

#define B   8
#define C   64
#define T   4096
#define KNN 9
#define MARGIN 1e-4f   // >> 2*eps of channel-pair reassociation (~1.2e-5)

typedef unsigned long long u64;

// Scratch (allocation-free: __device__ globals)
__device__ float g_qT[B * T * C];          // normalized q, [b][t][c]
__device__ float g_kT[B * T * C];          // normalized k, [b][t][c]
__device__ float g_vT[B * T * C];          // v, [b][t][c]
__device__ float g_wP[KNN * C * C];        // conv_w permuted: [kk][cc][o]
__device__ int   g_idx[B * T * KNN];       // top-9 neighbor indices per (b,i)

// ---------------------------------------------------------------------------
// Packed fp32x2 helpers (sm_100+): each lane is an exact IEEE rn fp32 op.
// ---------------------------------------------------------------------------
__device__ __forceinline__ u64 pk2(float lo, float hi) {
    u64 r; asm("mov.b64 %0, {%1, %2};" : "=l"(r) : "f"(lo), "f"(hi)); return r;
}
__device__ __forceinline__ u64 fma2(u64 a, u64 b, u64 c) {
    u64 d; asm("fma.rn.f32x2 %0, %1, %2, %3;" : "=l"(d) : "l"(a), "l"(b), "l"(c));
    return d;
}
__device__ __forceinline__ void unpk(u64 v, float& lo, float& hi) {
    asm("mov.b64 {%0, %1}, %2;" : "=f"(lo), "=f"(hi) : "l"(v));
}

// ---------------------------------------------------------------------------
// Kernel 0: permute conv_w[o][cc*9+kk] -> wP[kk][cc][o]
// ---------------------------------------------------------------------------
__global__ void permute_w_kernel(const float* __restrict__ conv_w) {
    int s = blockIdx.x * 256 + threadIdx.x;
    if (s < KNN * C * C) {
        int o  = s & 63;
        int cc = (s >> 6) & 63;
        int kk = s >> 12;
        g_wP[s] = conv_w[o * (C * KNN) + cc * KNN + kk];
    }
}

// ---------------------------------------------------------------------------
// Kernel 1: q/k/v projections + L2 normalize (k,q), write transposed [b][t][c]
// Numerics (validated in R3 at rel_err 5.3e-7): sequential fused FMA over c;
// separate mul+add sum-of-squares; IEEE division by fmax(sqrt, 1e-12).
// ---------------------------------------------------------------------------
__global__ __launch_bounds__(128) void proj_kernel(
    const float* __restrict__ x,
    const float* __restrict__ Wq,
    const float* __restrict__ Wk,
    const float* __restrict__ Wv)
{
    __shared__ float Xs[C][128];
    __shared__ float Ws[C][C];

    const int b   = blockIdx.y;
    const int t0  = blockIdx.x * 128;
    const int tid = threadIdx.x;

    const float* xb = x + (size_t)b * C * T;
    for (int c = 0; c < C; c++)
        Xs[c][tid] = xb[c * T + t0 + tid];

    for (int m = 0; m < 3; m++) {
        const float* W = (m == 0) ? Wq : ((m == 1) ? Wk : Wv);
        float* dstbase = (m == 0) ? g_qT : ((m == 1) ? g_kT : g_vT);

        __syncthreads();
        for (int s = tid; s < C * C; s += 128) {
            int c = s >> 6, d = s & 63;
            Ws[c][d] = W[d * C + c];
        }
        __syncthreads();

        float acc[C];
        #pragma unroll
        for (int d = 0; d < C; d++) acc[d] = 0.f;

        for (int c = 0; c < C; c++) {
            float xv = Xs[c][tid];
            const float4* wr = (const float4*)Ws[c];
            #pragma unroll
            for (int d4 = 0; d4 < 16; d4++) {
                float4 w = wr[d4];
                acc[4*d4+0] = __fmaf_rn(w.x, xv, acc[4*d4+0]);
                acc[4*d4+1] = __fmaf_rn(w.y, xv, acc[4*d4+1]);
                acc[4*d4+2] = __fmaf_rn(w.z, xv, acc[4*d4+2]);
                acc[4*d4+3] = __fmaf_rn(w.w, xv, acc[4*d4+3]);
            }
        }

        if (m < 2) {
            float ss = 0.f;
            #pragma unroll
            for (int d = 0; d < C; d++)
                ss = __fadd_rn(ss, __fmul_rn(acc[d], acc[d]));
            float n = fmaxf(sqrtf(ss), 1e-12f);
            #pragma unroll
            for (int d = 0; d < C; d++)
                acc[d] = __fdiv_rn(acc[d], n);
        }

        float4* dst = (float4*)(dstbase + ((size_t)b * T + t0 + tid) * C);
        #pragma unroll
        for (int d4 = 0; d4 < 16; d4++)
            dst[d4] = make_float4(acc[4*d4+0], acc[4*d4+1], acc[4*d4+2], acc[4*d4+3]);
    }
}

// ---------------------------------------------------------------------------
// Exact Top9 (strict > + ascending-index insertion = jax top_k tie-breaking)
// ---------------------------------------------------------------------------
struct Top9 {
    float v0,v1,v2,v3,v4,v5,v6,v7,v8;
    int   j0,j1,j2,j3,j4,j5,j6,j7,j8;
    __device__ __forceinline__ void init() {
        v0=v1=v2=v3=v4=v5=v6=v7=v8 = -1.f;
        j0=j1=j2=j3=j4=j5=j6=j7=j8 = 0;
    }
    __device__ __forceinline__ void insert(float s, int j) {
        if (s > v8) {
            v8 = s; j8 = j;
            #define _CSW(va,ja,vb,jb) if ((vb) > (va)) { float tv=(va); (va)=(vb); (vb)=tv; int tj=(ja); (ja)=(jb); (jb)=tj; }
            _CSW(v7,j7,v8,j8); _CSW(v6,j6,v7,j7); _CSW(v5,j5,v6,j6);
            _CSW(v4,j4,v5,j5); _CSW(v3,j3,v4,j4); _CSW(v2,j2,v3,j3);
            _CSW(v1,j1,v2,j2); _CSW(v0,j0,v1,j1);
            #undef _CSW
        }
    }
    __device__ __forceinline__ void store(int* op) {
        op[0]=j0; op[1]=j1; op[2]=j2; op[3]=j3; op[4]=j4;
        op[5]=j5; op[6]=j6; op[7]=j7; op[8]=j8;
    }
};

// ---------------------------------------------------------------------------
// exact sequential-chain dot (bitwise matches R3 / the reference ranking)
// ---------------------------------------------------------------------------
__device__ __forceinline__ float exact_dot(const float* __restrict__ kr,
                                           const float* __restrict__ qrow)
{
    const float4* q = (const float4*)qrow;
    float s = 0.f;
    #pragma unroll
    for (int c4 = 0; c4 < 16; c4++) {
        float4 qq = __ldg(&q[c4]);
        s = __fmaf_rn(kr[4*c4+0], qq.x, s);
        s = __fmaf_rn(kr[4*c4+1], qq.y, s);
        s = __fmaf_rn(kr[4*c4+2], qq.z, s);
        s = __fmaf_rn(kr[4*c4+3], qq.w, s);
    }
    return s;
}

// ---------------------------------------------------------------------------
// Kernel 2: approx prefilter (f32x2 channel-pair packing) -> top-16 ->
//           margin check -> exact sequential re-rank of 16 -> top-9.
// ---------------------------------------------------------------------------
__global__ __launch_bounds__(256) void sim_topk_kernel()
{
    __shared__ __align__(16) float Qs[64 * C];   // 16 KB, natural [j][c]

    const int b   = blockIdx.y;
    const int tid = threadIdx.x;
    const int i   = blockIdx.x * 256 + tid;

    // k row packed as (even,odd) channel pairs -- natural layout, 64 regs
    u64 kp[32];
    {
        const ulonglong2* kr2 = (const ulonglong2*)(g_kT + ((size_t)b * T + i) * C);
        #pragma unroll
        for (int c4 = 0; c4 < 16; c4++) {
            ulonglong2 t = kr2[c4];
            kp[2*c4]   = t.x;
            kp[2*c4+1] = t.y;
        }
    }

    // approx top-16 (register arrays; all accesses fully unrolled)
    float av[16]; int aj[16];
    #pragma unroll
    for (int m = 0; m < 16; m++) { av[m] = -1.f; aj[m] = 0; }

    for (int jt = 0; jt < T; jt += 64) {
        __syncthreads();
        #pragma unroll
        for (int u = 0; u < 4; u++) {
            int idx = u * 256 + tid;           // 1024 float4 = 64 rows x 16
            int j   = idx >> 4;
            int c4  = idx & 15;
            ((float4*)Qs)[idx] =
                ((const float4*)(g_qT + ((size_t)b * T + jt + j) * C))[c4];
        }
        __syncthreads();

        for (int jj = 0; jj < 64; jj += 4) {
            const ulonglong2* q0 = (const ulonglong2*)&Qs[(jj + 0) * C];
            const ulonglong2* q1 = (const ulonglong2*)&Qs[(jj + 1) * C];
            const ulonglong2* q2 = (const ulonglong2*)&Qs[(jj + 2) * C];
            const ulonglong2* q3 = (const ulonglong2*)&Qs[(jj + 3) * C];
            u64 s0 = 0ull, s1 = 0ull, s2 = 0ull, s3 = 0ull;
            #pragma unroll
            for (int c4 = 0; c4 < 16; c4++) {
                ulonglong2 a = q0[c4], bq = q1[c4], cq = q2[c4], dq = q3[c4];
                s0 = fma2(kp[2*c4],   a.x,  s0);
                s1 = fma2(kp[2*c4],   bq.x, s1);
                s2 = fma2(kp[2*c4],   cq.x, s2);
                s3 = fma2(kp[2*c4],   dq.x, s3);
                s0 = fma2(kp[2*c4+1], a.y,  s0);
                s1 = fma2(kp[2*c4+1], bq.y, s1);
                s2 = fma2(kp[2*c4+1], cq.y, s2);
                s3 = fma2(kp[2*c4+1], dq.y, s3);
            }
            #pragma unroll
            for (int g = 0; g < 4; g++) {
                float lo, hi;
                unpk(g == 0 ? s0 : (g == 1 ? s1 : (g == 2 ? s2 : s3)), lo, hi);
                float s = fmaxf(lo + hi, 0.f);
                if (s > av[15]) {
                    av[15] = s; aj[15] = jt + jj + g;
                    #pragma unroll
                    for (int m = 14; m >= 0; m--) {
                        if (av[m+1] > av[m]) {
                            float tv = av[m]; av[m] = av[m+1]; av[m+1] = tv;
                            int   tj = aj[m]; aj[m] = aj[m+1]; aj[m+1] = tj;
                        }
                    }
                }
            }
        }
    }

    // unpack k back to scalar floats (exact same fp32 values)
    float kr[C];
    #pragma unroll
    for (int c2 = 0; c2 < 32; c2++)
        unpk(kp[c2], kr[2*c2], kr[2*c2+1]);

    Top9 t9;
    t9.init();
    const float* qbase = g_qT + (size_t)b * T * C;

    if (av[15] >= av[8] - MARGIN) {
        // Fallback: proof that top16-approx covers top9-exact failed.
        // Exact full scan (statistically never taken).
        for (int j = 0; j < T; j++) {
            float s = fmaxf(exact_dot(kr, qbase + (size_t)j * C), 0.f);
            t9.insert(s, j);
        }
    } else {
        // sort the 16 candidate indices ascending (bubble, register-resident)
        #pragma unroll
        for (int a = 0; a < 15; a++)
            #pragma unroll
            for (int m = 0; m < 15; m++)
                if (aj[m] > aj[m+1]) { int tj = aj[m]; aj[m] = aj[m+1]; aj[m+1] = tj; }
        // exact re-rank in ascending-j order (reference tie-breaking)
        #pragma unroll
        for (int m = 0; m < 16; m++) {
            int j = aj[m];
            float s = fmaxf(exact_dot(kr, qbase + (size_t)j * C), 0.f);
            t9.insert(s, j);
        }
    }

    t9.store(g_idx + ((size_t)b * T + i) * KNN);
}

// ---------------------------------------------------------------------------
// Kernel 3: gather v + 1x1 conv (576 -> 64) + bias, f32x2 over output pairs.
// (unchanged from R4: 109.6 -> 92.0 us)
// ---------------------------------------------------------------------------
__global__ __launch_bounds__(128) void gather_conv_kernel(
    const float* __restrict__ conv_b,
    float* __restrict__ out)
{
    __shared__ float  Ws[C * C];          // 16 KB, [cc][o] for current kk
    __shared__ float4 Vs[4][16][33];      // per warp: [c4][row], padded

    const int b   = blockIdx.y;
    const int tid = threadIdx.x;
    const int w   = tid >> 5;
    const int l   = tid & 31;
    const int i   = blockIdx.x * 128 + tid;

    u64 accp[32];
    #pragma unroll
    for (int o2 = 0; o2 < 32; o2++) accp[o2] = 0ull;

    const int base = (b * T + i) * KNN;

    for (int kk = 0; kk < KNN; kk++) {
        __syncthreads();
        {
            const float4* wsrc = (const float4*)(g_wP + kk * C * C);
            float4* wdst = (float4*)Ws;
            #pragma unroll
            for (int r = 0; r < 8; r++)
                wdst[r * 128 + tid] = wsrc[r * 128 + tid];
        }

        int j = g_idx[base + kk];

        #pragma unroll
        for (int rp = 0; rp < 32; rp += 2) {
            int r  = rp + (l >> 4);
            int c4 = l & 15;
            int jr = __shfl_sync(0xffffffffu, j, r);
            float4 vv = ((const float4*)(g_vT + ((size_t)b * T + jr) * C))[c4];
            Vs[w][c4][r] = vv;
        }
        __syncthreads();

        #pragma unroll
        for (int c4 = 0; c4 < 16; c4++) {
            float4 xv = Vs[w][c4][l];
            float xs[4] = {xv.x, xv.y, xv.z, xv.w};
            #pragma unroll
            for (int e = 0; e < 4; e++) {
                u64 xd = pk2(xs[e], xs[e]);
                const ulonglong2* wr = (const ulonglong2*)(Ws + (c4 * 4 + e) * C);
                #pragma unroll
                for (int o4 = 0; o4 < 16; o4++) {
                    ulonglong2 wp = wr[o4];
                    accp[2*o4+0] = fma2(xd, wp.x, accp[2*o4+0]);
                    accp[2*o4+1] = fma2(xd, wp.y, accp[2*o4+1]);
                }
            }
        }
    }

    #pragma unroll
    for (int o2 = 0; o2 < 32; o2++) {
        float f0, f1;
        unpk(accp[o2], f0, f1);
        out[((size_t)(b * C + 2*o2 + 0)) * T + i] = f0 + __ldg(&conv_b[2*o2 + 0]);
        out[((size_t)(b * C + 2*o2 + 1)) * T + i] = f1 + __ldg(&conv_b[2*o2 + 1]);
    }
}

// ---------------------------------------------------------------------------
extern "C" void kernel_launch(void* const* d_in, const int* in_sizes, int n_in,
                              void* d_out, int out_size)
{
    const float* x      = (const float*)d_in[0];
    const float* Wq     = (const float*)d_in[1];
    const float* Wk     = (const float*)d_in[2];
    const float* Wv     = (const float*)d_in[3];
    const float* conv_w = (const float*)d_in[4];
    const float* conv_b = (const float*)d_in[5];
    float* out          = (float*)d_out;

    permute_w_kernel<<<(KNN * C * C + 255) / 256, 256>>>(conv_w);
    proj_kernel<<<dim3(T / 128, B), 128>>>(x, Wq, Wk, Wv);
    sim_topk_kernel<<<dim3(T / 256, B), 256>>>();
    gather_conv_kernel<<<dim3(T / 128, B), 128>>>(conv_b, out);
}

// round 8
// speedup vs baseline: 1.2850x; 1.2850x over previous
#include <cuda_runtime.h>
#include <cuda_bf16.h>
#include <stdint.h>
#include <math.h>

#define B      8
#define C      64
#define T      4096
#define KNN    9
#define NTILES (T / 128)      // 32 j-tiles of 128
#define NLANE  12             // per-(thread,row) approx list depth
#define MMERGE 24             // merged per-row shortlist depth
#define ERRB   0.006f         // >= rigorous bf16 product bound 2^-8 = 0.0039

typedef unsigned long long u64;
typedef unsigned int       u32;

// Scratch (allocation-free: __device__ globals)
__device__ float g_qT[B * T * C];                         // normalized q fp32 [b][t][c]
__device__ float g_kT[B * T * C];                         // normalized k fp32
__device__ float g_vT[B * T * C];                         // v fp32
__device__ __align__(16) __nv_bfloat16 g_qB[B * T * C];   // bf16 copy of g_qT
__device__ __align__(16) __nv_bfloat16 g_kB[B * T * C];   // bf16 copy of g_kT
__device__ float g_wP[KNN * C * C];                       // conv_w permuted [kk][cc][o]
__device__ int   g_idx[B * T * KNN];                      // top-9 indices per (b,i)

// smem layout constants (bytes, within dynamic smem)
#define A_OFF    0             // 128 rows x 144B = 18432
#define B_OFF    18432         // 128 rows x 144B = 18432   (main phase)
#define LIST_OFF 0             // [8 warps][32 lanes][2][12] u64 = 49152 (overlay)
#define MK_OFF   49152         // [8][16][24] u64 = 24576
#define ACUT_OFF 73728         // [8][16] float = 512
#define SMEM_SZ  74240
#define STG_STRIDE 68          // floats per staged row (rerank)

// ---------------------------------------------------------------------------
// helpers
// ---------------------------------------------------------------------------
__device__ __forceinline__ u32 smem_u32(const void* p) {
    u32 a;
    asm("{ .reg .u64 t; cvta.to.shared.u64 t, %1; cvt.u32.u64 %0, t; }"
        : "=r"(a) : "l"(p));
    return a;
}
__device__ __forceinline__ u64 pk2(float lo, float hi) {
    u64 r; asm("mov.b64 %0, {%1, %2};" : "=l"(r) : "f"(lo), "f"(hi)); return r;
}
__device__ __forceinline__ u64 fma2(u64 a, u64 b, u64 c) {
    u64 d; asm("fma.rn.f32x2 %0, %1, %2, %3;" : "=l"(d) : "l"(a), "l"(b), "l"(c));
    return d;
}
__device__ __forceinline__ void unpk(u64 v, float& lo, float& hi) {
    asm("mov.b64 {%0, %1}, %2;" : "=f"(lo), "=f"(hi) : "l"(v));
}
__device__ __forceinline__ void ldm4(u32* r, u32 addr) {
    asm volatile("ldmatrix.sync.aligned.m8n8.x4.shared.b16 {%0,%1,%2,%3}, [%4];"
                 : "=r"(r[0]), "=r"(r[1]), "=r"(r[2]), "=r"(r[3]) : "r"(addr));
}
__device__ __forceinline__ void mma16816(float* c, const u32* a, const u32* b) {
    asm volatile("mma.sync.aligned.m16n8k16.row.col.f32.bf16.bf16.f32 "
                 "{%0,%1,%2,%3}, {%4,%5,%6,%7}, {%8,%9}, {%0,%1,%2,%3};"
                 : "+f"(c[0]), "+f"(c[1]), "+f"(c[2]), "+f"(c[3])
                 : "r"(a[0]), "r"(a[1]), "r"(a[2]), "r"(a[3]),
                   "r"(b[0]), "r"(b[1]));
}

// ---------------------------------------------------------------------------
// Kernel 0: permute conv_w[o][cc*9+kk] -> wP[kk][cc][o]
// ---------------------------------------------------------------------------
__global__ void permute_w_kernel(const float* __restrict__ conv_w) {
    int s = blockIdx.x * 256 + threadIdx.x;
    if (s < KNN * C * C) {
        int o  = s & 63;
        int cc = (s >> 6) & 63;
        int kk = s >> 12;
        g_wP[s] = conv_w[o * (C * KNN) + cc * KNN + kk];
    }
}

// ---------------------------------------------------------------------------
// Kernel 1: q/k/v projections + L2 normalize (k,q); fp32 + bf16 outputs.
// Numerics validated at rel_err 5.3e-7 in R3.
// ---------------------------------------------------------------------------
__global__ __launch_bounds__(128) void proj_kernel(
    const float* __restrict__ x,
    const float* __restrict__ Wq,
    const float* __restrict__ Wk,
    const float* __restrict__ Wv)
{
    __shared__ float Xs[C][128];
    __shared__ float Ws[C][C];

    const int b   = blockIdx.y;
    const int t0  = blockIdx.x * 128;
    const int tid = threadIdx.x;

    const float* xb = x + (size_t)b * C * T;
    for (int c = 0; c < C; c++)
        Xs[c][tid] = xb[c * T + t0 + tid];

    for (int m = 0; m < 3; m++) {
        const float* W = (m == 0) ? Wq : ((m == 1) ? Wk : Wv);
        float* dstbase = (m == 0) ? g_qT : ((m == 1) ? g_kT : g_vT);

        __syncthreads();
        for (int s = tid; s < C * C; s += 128) {
            int c = s >> 6, d = s & 63;
            Ws[c][d] = W[d * C + c];
        }
        __syncthreads();

        float acc[C];
        #pragma unroll
        for (int d = 0; d < C; d++) acc[d] = 0.f;

        for (int c = 0; c < C; c++) {
            float xv = Xs[c][tid];
            const float4* wr = (const float4*)Ws[c];
            #pragma unroll
            for (int d4 = 0; d4 < 16; d4++) {
                float4 w = wr[d4];
                acc[4*d4+0] = __fmaf_rn(w.x, xv, acc[4*d4+0]);
                acc[4*d4+1] = __fmaf_rn(w.y, xv, acc[4*d4+1]);
                acc[4*d4+2] = __fmaf_rn(w.z, xv, acc[4*d4+2]);
                acc[4*d4+3] = __fmaf_rn(w.w, xv, acc[4*d4+3]);
            }
        }

        if (m < 2) {
            float ss = 0.f;
            #pragma unroll
            for (int d = 0; d < C; d++)
                ss = __fadd_rn(ss, __fmul_rn(acc[d], acc[d]));
            float n = fmaxf(sqrtf(ss), 1e-12f);
            #pragma unroll
            for (int d = 0; d < C; d++)
                acc[d] = __fdiv_rn(acc[d], n);
        }

        float4* dst = (float4*)(dstbase + ((size_t)b * T + t0 + tid) * C);
        #pragma unroll
        for (int d4 = 0; d4 < 16; d4++)
            dst[d4] = make_float4(acc[4*d4+0], acc[4*d4+1], acc[4*d4+2], acc[4*d4+3]);

        if (m < 2) {
            __nv_bfloat16* bb = (m == 0) ? g_qB : g_kB;
            __nv_bfloat162* bd = (__nv_bfloat162*)(bb + ((size_t)b * T + t0 + tid) * C);
            #pragma unroll
            for (int d2 = 0; d2 < 32; d2++)
                bd[d2] = __floats2bfloat162_rn(acc[2*d2], acc[2*d2+1]);
        }
    }
}

// ---------------------------------------------------------------------------
// Lex Top9: value desc, index asc on ties (== jax top_k). Any insert order.
// ---------------------------------------------------------------------------
struct Top9 {
    float v0,v1,v2,v3,v4,v5,v6,v7,v8;
    int   j0,j1,j2,j3,j4,j5,j6,j7,j8;
    __device__ __forceinline__ void init() {
        v0=v1=v2=v3=v4=v5=v6=v7=v8 = -1.f;
        j0=j1=j2=j3=j4=j5=j6=j7=j8 = 0x7FFFFFFF;
    }
    __device__ __forceinline__ void insert(float s, int j) {
        if ((s > v8) || (s == v8 && j < j8)) {
            v8 = s; j8 = j;
            #define _LSW(va,ja,vb,jb) if (((vb) > (va)) || ((vb) == (va) && (jb) < (ja))) { \
                float tv=(va); (va)=(vb); (vb)=tv; int tj=(ja); (ja)=(jb); (jb)=tj; }
            _LSW(v7,j7,v8,j8); _LSW(v6,j6,v7,j7); _LSW(v5,j5,v6,j6);
            _LSW(v4,j4,v5,j5); _LSW(v3,j3,v4,j4); _LSW(v2,j2,v3,j3);
            _LSW(v1,j1,v2,j2); _LSW(v0,j0,v1,j1);
            #undef _LSW
        }
    }
    __device__ __forceinline__ void store(int* op) {
        op[0]=j0; op[1]=j1; op[2]=j2; op[3]=j3; op[4]=j4;
        op[5]=j5; op[6]=j6; op[7]=j7; op[8]=j8;
    }
};

__device__ __forceinline__ float exact_dot_g(const float* __restrict__ kr,
                                             const float* __restrict__ qrow)
{
    const float4* q = (const float4*)qrow;
    float s = 0.f;
    #pragma unroll
    for (int c4 = 0; c4 < 16; c4++) {
        float4 qq = __ldg(&q[c4]);
        s = __fmaf_rn(kr[4*c4+0], qq.x, s);
        s = __fmaf_rn(kr[4*c4+1], qq.y, s);
        s = __fmaf_rn(kr[4*c4+2], qq.z, s);
        s = __fmaf_rn(kr[4*c4+3], qq.w, s);
    }
    return s;
}

// approx-list insert: keys sorted desc; gate on value only (ties droppable —
// coverage bound uses <=). offset domain val' = clamp(val)+1 > 0.
#define PROC_SCORE(val, KL, MN, jj) do {                                      \
    float s_ = fmaxf((val), 0.f) + 1.0f;                                      \
    if (s_ > (MN)) {                                                          \
        u64 key_ = ((u64)__float_as_uint(s_) << 32) | (u32)(0xFFFFu - (u32)(jj)); \
        KL[11] = key_;                                                        \
        _Pragma("unroll")                                                     \
        for (int z_ = 10; z_ >= 0; z_--)                                      \
            if (KL[z_+1] > KL[z_]) { u64 t_ = KL[z_]; KL[z_] = KL[z_+1]; KL[z_+1] = t_; } \
        MN = __uint_as_float((u32)(KL[11] >> 32));                            \
    } } while (0)

// ---------------------------------------------------------------------------
// Kernel 2: bf16 mma.sync prefilter -> per-row top-24 shortlist ->
//           exact fp32 re-rank -> lex Top9 (+ sound margin check/fallback).
// 256 threads = 8 warps; warp w owns i-rows i0 + w*16 .. +15.
// ---------------------------------------------------------------------------
__global__ __launch_bounds__(256) void sim_topk_mma_kernel()
{
    extern __shared__ __align__(16) char dynsmem[];

    const int b    = blockIdx.y;
    const int tid  = threadIdx.x;
    const int w    = tid >> 5;
    const int lane = tid & 31;
    const int i0   = blockIdx.x * 128;

    const u32 sb = smem_u32(dynsmem);

    // ---- stage A: 128 k-rows bf16 -> smem rows of 144B ----
    {
        const uint4* src = (const uint4*)(g_kB + ((size_t)b * T + i0) * C);
        #pragma unroll
        for (int it = 0; it < 4; it++) {
            int idx = it * 256 + tid;
            int row = idx >> 3, ch = idx & 7;
            uint4 v = __ldg(src + row * 8 + ch);
            *(uint4*)(dynsmem + A_OFF + row * 144 + ch * 16) = v;
        }
    }
    __syncthreads();

    // ---- A fragments (warp's 16 rows, 4 k-steps) ----
    u32 afr[4][4];
    {
        u32 abase = sb + A_OFF + (w * 16 + (lane & 15)) * 144 + (lane >> 4) * 16;
        #pragma unroll
        for (int ks = 0; ks < 4; ks++) ldm4(afr[ks], abase + ks * 32);
    }

    // per-(thread,row-half) approx top-12 lists as packed u64 keys
    u64 kl0[NLANE], kl1[NLANE];
    float mn0 = 0.f, mn1 = 0.f;
    #pragma unroll
    for (int m = 0; m < NLANE; m++) { kl0[m] = 0ull; kl1[m] = 0ull; }

    const int jrow  = (lane & 7) + ((lane >> 4) << 3);
    const int khalf = (lane >> 3) & 1;
    const int q0    = 2 * (lane & 3);

    for (int t = 0; t < NTILES; t++) {
        __syncthreads();
        {   // stage B: 128 q-rows of tile t
            const uint4* src = (const uint4*)(g_qB + ((size_t)b * T + (size_t)t * 128) * C);
            #pragma unroll
            for (int it = 0; it < 4; it++) {
                int idx = it * 256 + tid;
                int row = idx >> 3, ch = idx & 7;
                uint4 v = __ldg(src + row * 8 + ch);
                *(uint4*)(dynsmem + B_OFF + row * 144 + ch * 16) = v;
            }
        }
        __syncthreads();

        #pragma unroll 2
        for (int chunk = 0; chunk < 8; chunk++) {
            u32 bbase = sb + B_OFF + (chunk * 16 + jrow) * 144 + khalf * 16;
            float a0[4] = {0.f, 0.f, 0.f, 0.f};
            float a1[4] = {0.f, 0.f, 0.f, 0.f};
            #pragma unroll
            for (int ks = 0; ks < 4; ks++) {
                u32 bb[4];
                ldm4(bb, bbase + ks * 32);
                mma16816(a0, afr[ks], bb + 0);   // n-tile 0 (j .. +0..7)
                mma16816(a1, afr[ks], bb + 2);   // n-tile 1 (j .. +8..15)
            }
            int jb = t * 128 + chunk * 16 + q0;
            PROC_SCORE(a0[0], kl0, mn0, jb + 0);
            PROC_SCORE(a0[1], kl0, mn0, jb + 1);
            PROC_SCORE(a0[2], kl1, mn1, jb + 0);
            PROC_SCORE(a0[3], kl1, mn1, jb + 1);
            PROC_SCORE(a1[0], kl0, mn0, jb + 8);
            PROC_SCORE(a1[1], kl0, mn0, jb + 9);
            PROC_SCORE(a1[2], kl1, mn1, jb + 8);
            PROC_SCORE(a1[3], kl1, mn1, jb + 9);
        }
    }

    // ---- dump lists to smem (overlays A/B) ----
    __syncthreads();
    u64* LST = (u64*)(dynsmem + LIST_OFF);
    {
        u64* my = LST + (size_t)(w * 32 + lane) * (2 * NLANE);
        #pragma unroll
        for (int m = 0; m < NLANE; m++) { my[m] = kl0[m]; my[NLANE + m] = kl1[m]; }
    }
    __syncwarp();

    // ---- warp-local merge: leaders build per-row top-24 + acut ----
    u64*   MK  = (u64*)(dynsmem + MK_OFF);
    float* ACT = (float*)(dynsmem + ACUT_OFF);
    if ((lane & 1) == 0) {
        int r    = lane >> 2;
        int half = (lane >> 1) & 1;
        int rrow = r + half * 8;
        u64* mk  = MK + (size_t)(w * 16 + rrow) * MMERGE;
        #pragma unroll
        for (int m = 0; m < MMERGE; m++) mk[m] = 0ull;
        float acut = 0.f;
        for (int src = 0; src < 4; src++) {
            const u64* L = LST + (size_t)(w * 32 + r * 4 + src) * (2 * NLANE) + half * NLANE;
            acut = fmaxf(acut, __uint_as_float((u32)(L[NLANE - 1] >> 32)));
            for (int e = 0; e < NLANE; e++) {
                u64 key = L[e];
                if (!(key >> 32)) break;          // sorted desc; rest are sentinels
                if (key <= mk[MMERGE - 1]) continue;
                mk[MMERGE - 1] = key;
                for (int z = MMERGE - 2; z >= 0; z--) {
                    if (mk[z + 1] > mk[z]) { u64 tk = mk[z]; mk[z] = mk[z + 1]; mk[z + 1] = tk; }
                    else break;
                }
            }
        }
        acut = fmaxf(acut, __uint_as_float((u32)(mk[MMERGE - 1] >> 32)));
        ACT[w * 16 + rrow] = acut;
    }
    __syncwarp();

    // ---- exact re-rank ----
    float kr[C];
    if (lane < 16) {
        const float4* kp4 = (const float4*)(g_kT + ((size_t)b * T + i0 + w * 16 + lane) * C);
        #pragma unroll
        for (int c4 = 0; c4 < 16; c4++) {
            float4 k4 = __ldg(&kp4[c4]);
            kr[4*c4+0] = k4.x; kr[4*c4+1] = k4.y;
            kr[4*c4+2] = k4.z; kr[4*c4+3] = k4.w;
        }
    }

    Top9 t9;
    t9.init();
    float* stg = (float*)(dynsmem + (size_t)w * 6144);   // own list region (dead)

    for (int m = 0; m < MMERGE; m++) {
        __syncwarp();
        // stage candidate m's q row for all 16 warp-rows (coalesced)
        #pragma unroll
        for (int it = 0; it < 8; it++) {
            int idx = it * 32 + lane;
            int r = idx >> 4, c4 = idx & 15;
            u64 key = MK[(size_t)(w * 16 + r) * MMERGE + m];
            int jc = (key >> 32) ? (int)(0xFFFFu - (u32)(key & 0xFFFFu)) : 0;
            float4 qv = __ldg((const float4*)(g_qT + ((size_t)b * T + jc) * C) + c4);
            *(float4*)(stg + r * STG_STRIDE + c4 * 4) = qv;
        }
        __syncwarp();
        if (lane < 16) {
            u64 key = MK[(size_t)(w * 16 + lane) * MMERGE + m];
            if (key >> 32) {
                int jc = (int)(0xFFFFu - (u32)(key & 0xFFFFu));
                const float4* qs = (const float4*)(stg + lane * STG_STRIDE);
                float s = 0.f;
                #pragma unroll
                for (int c4 = 0; c4 < 16; c4++) {
                    float4 q = qs[c4];
                    s = __fmaf_rn(kr[4*c4+0], q.x, s);
                    s = __fmaf_rn(kr[4*c4+1], q.y, s);
                    s = __fmaf_rn(kr[4*c4+2], q.z, s);
                    s = __fmaf_rn(kr[4*c4+3], q.w, s);
                }
                t9.insert(fmaxf(s, 0.f), jc);
            }
        }
    }

    if (lane < 16) {
        float acut = ACT[w * 16 + lane];
        // coverage: excluded j have clamp(approx)+1 <= acut, so exact <= acut-1+ERRB
        if (acut - 1.0f + ERRB >= t9.v8) {
            t9.init();
            const float* qb = g_qT + (size_t)b * T * C;
            for (int j = 0; j < T; j++) {
                float s = fmaxf(exact_dot_g(kr, qb + (size_t)j * C), 0.f);
                t9.insert(s, j);
            }
        }
        t9.store(g_idx + ((size_t)b * T + i0 + w * 16 + lane) * KNN);
    }
}

// ---------------------------------------------------------------------------
// Kernel 3: gather v + 1x1 conv (576 -> 64) + bias (R4 version, 92us)
// ---------------------------------------------------------------------------
__global__ __launch_bounds__(128) void gather_conv_kernel(
    const float* __restrict__ conv_b,
    float* __restrict__ out)
{
    __shared__ float  Ws[C * C];
    __shared__ float4 Vs[4][16][33];

    const int b   = blockIdx.y;
    const int tid = threadIdx.x;
    const int w   = tid >> 5;
    const int l   = tid & 31;
    const int i   = blockIdx.x * 128 + tid;

    u64 accp[32];
    #pragma unroll
    for (int o2 = 0; o2 < 32; o2++) accp[o2] = 0ull;

    const int base = (b * T + i) * KNN;

    for (int kk = 0; kk < KNN; kk++) {
        __syncthreads();
        {
            const float4* wsrc = (const float4*)(g_wP + kk * C * C);
            float4* wdst = (float4*)Ws;
            #pragma unroll
            for (int r = 0; r < 8; r++)
                wdst[r * 128 + tid] = wsrc[r * 128 + tid];
        }

        int j = g_idx[base + kk];

        #pragma unroll
        for (int rp = 0; rp < 32; rp += 2) {
            int r  = rp + (l >> 4);
            int c4 = l & 15;
            int jr = __shfl_sync(0xffffffffu, j, r);
            float4 vv = ((const float4*)(g_vT + ((size_t)b * T + jr) * C))[c4];
            Vs[w][c4][r] = vv;
        }
        __syncthreads();

        #pragma unroll
        for (int c4 = 0; c4 < 16; c4++) {
            float4 xv = Vs[w][c4][l];
            float xs[4] = {xv.x, xv.y, xv.z, xv.w};
            #pragma unroll
            for (int e = 0; e < 4; e++) {
                u64 xd = pk2(xs[e], xs[e]);
                const ulonglong2* wr = (const ulonglong2*)(Ws + (c4 * 4 + e) * C);
                #pragma unroll
                for (int o4 = 0; o4 < 16; o4++) {
                    ulonglong2 wp = wr[o4];
                    accp[2*o4+0] = fma2(xd, wp.x, accp[2*o4+0]);
                    accp[2*o4+1] = fma2(xd, wp.y, accp[2*o4+1]);
                }
            }
        }
    }

    #pragma unroll
    for (int o2 = 0; o2 < 32; o2++) {
        float f0, f1;
        unpk(accp[o2], f0, f1);
        out[((size_t)(b * C + 2*o2 + 0)) * T + i] = f0 + __ldg(&conv_b[2*o2 + 0]);
        out[((size_t)(b * C + 2*o2 + 1)) * T + i] = f1 + __ldg(&conv_b[2*o2 + 1]);
    }
}

// ---------------------------------------------------------------------------
extern "C" void kernel_launch(void* const* d_in, const int* in_sizes, int n_in,
                              void* d_out, int out_size)
{
    const float* x      = (const float*)d_in[0];
    const float* Wq     = (const float*)d_in[1];
    const float* Wk     = (const float*)d_in[2];
    const float* Wv     = (const float*)d_in[3];
    const float* conv_w = (const float*)d_in[4];
    const float* conv_b = (const float*)d_in[5];
    float* out          = (float*)d_out;

    cudaFuncSetAttribute(sim_topk_mma_kernel,
                         cudaFuncAttributeMaxDynamicSharedMemorySize, SMEM_SZ);

    permute_w_kernel<<<(KNN * C * C + 255) / 256, 256>>>(conv_w);
    proj_kernel<<<dim3(T / 128, B), 128>>>(x, Wq, Wk, Wv);
    sim_topk_mma_kernel<<<dim3(T / 128, B), 256, SMEM_SZ>>>();
    gather_conv_kernel<<<dim3(T / 128, B), 128>>>(conv_b, out);
}